// round 8
// baseline (speedup 1.0000x reference)
#include <cuda_runtime.h>
#include <cstdint>

#define HIDDEN 4096
#define INTER  11008
#define MTOT   8192
#define LDA1   8192          // K' bytes per x-digit row (2 * HIDDEN)
#define LDA2   22016         // K' bytes per h-digit row (2 * INTER)
#define F1     9.84251968503937e-4f   /* s_x/64 = 8/(127*64) */
#define INV_SX 15.875f                /* 127/8 */

// ---------------------------------------------------------------------------
// Device-global scratch (allocation rule: __device__ arrays only)
// ---------------------------------------------------------------------------
__device__ int8_t g_x8[(size_t)MTOT * LDA1];     // x digits interleaved (d0,d1)
__device__ int8_t g_wg8[(size_t)INTER * HIDDEN]; // ternary s8
__device__ int8_t g_wu8[(size_t)INTER * HIDDEN];
__device__ int8_t g_wd8[(size_t)HIDDEN * INTER];
__device__ float  g_h[(size_t)MTOT * INTER];     // SwiGLU output fp32
__device__ int8_t g_h8[(size_t)MTOT * LDA2];     // h digits interleaved
__device__ int    g_rowmax[MTOT];                // per-token max|h| (float bits)
__device__ float  g_sh[MTOT];                    // per-token dequant factor s_t/64

// ---------------------------------------------------------------------------
// Helpers
// ---------------------------------------------------------------------------
__device__ __forceinline__ uint32_t smem_u32(const void* p) {
    uint32_t a;
    asm("{ .reg .u64 t; cvta.to.shared.u64 t, %1; cvt.u32.u64 %0, t; }"
        : "=r"(a) : "l"(p));
    return a;
}
__device__ __forceinline__ void cp16(uint32_t dst, const void* src) {
    asm volatile("cp.async.cg.shared.global [%0], [%1], 16;" :: "r"(dst), "l"(src));
}
#define CP_COMMIT() asm volatile("cp.async.commit_group;")
#define CP_WAIT0()  asm volatile("cp.async.wait_group 0;")

// m16n8k32 s8 MMA, s32 accumulate
#define MMA_S8(c, a, b)                                                     \
    asm volatile("mma.sync.aligned.m16n8k32.row.col.s32.s8.s8.s32 "         \
        "{%0,%1,%2,%3}, {%4,%5,%6,%7}, {%8,%9}, {%0,%1,%2,%3};"             \
        : "+r"((c)[0]), "+r"((c)[1]), "+r"((c)[2]), "+r"((c)[3])            \
        : "r"((a)[0]), "r"((a)[1]), "r"((a)[2]), "r"((a)[3]),               \
          "r"((b)[0]), "r"((b)[1]))

// Expand 16 ternary w bytes -> 32 bytes of (64w, w) pairs into SMEM
__device__ __forceinline__ void expand_sts(char* dst, uint4 p) {
    uint32_t w[4] = {p.x, p.y, p.z, p.w};
    uint32_t o[8];
#pragma unroll
    for (int i = 0; i < 4; ++i) {
        uint32_t q = (w[i] << 6) & 0xC0C0C0C0u;   // per-byte 64*w
        o[2*i]   = __byte_perm(q, w[i], 0x5140);  // [64w0,w0,64w1,w1]
        o[2*i+1] = __byte_perm(q, w[i], 0x7362);  // [64w2,w2,64w3,w3]
    }
    reinterpret_cast<uint4*>(dst)[0] = make_uint4(o[0], o[1], o[2], o[3]);
    reinterpret_cast<uint4*>(dst)[1] = make_uint4(o[4], o[5], o[6], o[7]);
}

// ---------------------------------------------------------------------------
// Conversions
// ---------------------------------------------------------------------------
__device__ __forceinline__ uint32_t pack_s8x4(float a, float b, float c, float d) {
    int x0 = (int)rintf(a) & 0xFF, x1 = (int)rintf(b) & 0xFF;
    int x2 = (int)rintf(c) & 0xFF, x3 = (int)rintf(d) & 0xFF;
    return (uint32_t)(x0 | (x1 << 8) | (x2 << 16) | (x3 << 24));
}

__global__ void convert_w_kernel(const float* __restrict__ wg,
                                 const float* __restrict__ wu,
                                 const float* __restrict__ wd) {
    size_t i = ((size_t)blockIdx.x * blockDim.x + threadIdx.x) * 4;
    if (i >= (size_t)INTER * HIDDEN) return;
    float4 a = *reinterpret_cast<const float4*>(wg + i);
    *reinterpret_cast<uint32_t*>(g_wg8 + i) = pack_s8x4(a.x, a.y, a.z, a.w);
    float4 b = *reinterpret_cast<const float4*>(wu + i);
    *reinterpret_cast<uint32_t*>(g_wu8 + i) = pack_s8x4(b.x, b.y, b.z, b.w);
    float4 c = *reinterpret_cast<const float4*>(wd + i);
    *reinterpret_cast<uint32_t*>(g_wd8 + i) = pack_s8x4(c.x, c.y, c.z, c.w);
}

__device__ __forceinline__ uint32_t digit_pair2(float v0, float v1) {
    // returns bytes (d0(v0), d1(v0), d0(v1), d1(v1))
    float t0 = fminf(fmaxf(v0 * INV_SX, -127.f), 127.f);
    float d0 = rintf(t0);
    float e0 = rintf((t0 - d0) * 64.f);
    float t1 = fminf(fmaxf(v1 * INV_SX, -127.f), 127.f);
    float d1 = rintf(t1);
    float e1 = rintf((t1 - d1) * 64.f);
    return pack_s8x4(d0, e0, d1, e1);
}

__global__ void convert_x_kernel(const float* __restrict__ x) {
    size_t gid = (size_t)blockIdx.x * blockDim.x + threadIdx.x;
    if (gid < MTOT) g_rowmax[gid] = 0;           // re-init rowmax every run
    size_t i = gid * 4;
    if (i >= (size_t)MTOT * HIDDEN) return;
    float4 v = *reinterpret_cast<const float4*>(x + i);
    uint2 o;
    o.x = digit_pair2(v.x, v.y);
    o.y = digit_pair2(v.z, v.w);
    *reinterpret_cast<uint2*>(g_x8 + 2 * i) = o;
}

// per-token quantize of h with per-row scale
__global__ void quantize_h_kernel() {
    int r = blockIdx.x;
    float rowmax = __int_as_float(g_rowmax[r]);
    float sinv = rowmax > 0.f ? 127.f / rowmax : 0.f;
    if (threadIdx.x == 0) g_sh[r] = rowmax * (1.0f / 8128.0f);  // s_t/64
    const float* hrow = g_h + (size_t)r * INTER;
    int8_t* drow = g_h8 + (size_t)r * LDA2;
    for (int c = threadIdx.x; c < INTER / 4; c += blockDim.x) {
        float4 v = *reinterpret_cast<const float4*>(hrow + c * 4);
        uint2 o;
        {
            float t0 = v.x * sinv, t1 = v.y * sinv;
            float d0 = rintf(t0), d1 = rintf(t1);
            o.x = pack_s8x4(d0, rintf((t0 - d0) * 64.f), d1, rintf((t1 - d1) * 64.f));
        }
        {
            float t0 = v.z * sinv, t1 = v.w * sinv;
            float d0 = rintf(t0), d1 = rintf(t1);
            o.y = pack_s8x4(d0, rintf((t0 - d0) * 64.f), d1, rintf((t1 - d1) * 64.f));
        }
        *reinterpret_cast<uint2*>(drow + c * 8) = o;
    }
}

// ---------------------------------------------------------------------------
// GEMM1: gate/up + fused SwiGLU -> g_h (fp32) + rowmax.
// CTA 128M x 128N computing BOTH gate and up. 8 warps (2x4), warp 64x32.
// Stage = K'128 bytes (64 orig k). SMEM pitch 144 (conflict-free).
//   stage layout: A[128x144] | Bg[128x144] | Bu[128x144] = 55296 B, x2 stages
// ---------------------------------------------------------------------------
#define PITCH   144
#define G1_STG  55296
#define G1_SMEM (1024 + 2 * G1_STG)
#define G1_S    64                  /* 4096/64 stages */

__global__ void __launch_bounds__(256, 1)
gemm1_kernel(const float* __restrict__ ag, const float* __restrict__ au) {
    extern __shared__ char sm[];
    const int tid = threadIdx.x;
    const int warp = tid >> 5, lane = tid & 31;
    const int wm = warp >> 2, wn = warp & 3;
    const int g = lane >> 2, tg = lane & 3;

    int bid = blockIdx.x;
    int grp = bid / 688, rem = bid % 688;     // 688 = 8 * 86
    int mt = grp * 8 + (rem & 7);
    int nt = rem >> 3;

    float* s_ag = reinterpret_cast<float*>(sm);
    float* s_au = reinterpret_cast<float*>(sm + 512);
    if (tid < 128) {
        s_ag[tid] = ag[nt * 128 + tid];
        s_au[tid] = au[nt * 128 + tid];
    }

    const int8_t* Ab = g_x8 + (size_t)mt * 128 * LDA1;
    const int8_t* Gb = g_wg8 + (size_t)nt * 128 * HIDDEN;
    const int8_t* Ub = g_wu8 + (size_t)nt * 128 * HIDDEN;
    const uint32_t sb = smem_u32(sm) + 1024;

    int cg[4][4][4], cu[4][4][4];
#pragma unroll
    for (int i = 0; i < 4; ++i)
#pragma unroll
        for (int j = 0; j < 4; ++j)
#pragma unroll
            for (int k = 0; k < 4; ++k) { cg[i][j][k] = 0; cu[i][j][k] = 0; }

    // ---- prologue: stage 0 ----
#pragma unroll
    for (int j = 0; j < 4; ++j) {
        int task = tid + j * 256, row = task >> 3, ch = task & 7;
        cp16(sb + row * PITCH + ch * 16, Ab + (size_t)row * LDA1 + ch * 16);
    }
    CP_COMMIT();
#pragma unroll
    for (int j = 0; j < 2; ++j) {
        int task = tid + j * 256, row = task >> 2, ch = task & 3;
        uint4 pg = *reinterpret_cast<const uint4*>(Gb + (size_t)row * HIDDEN + ch * 16);
        uint4 pu = *reinterpret_cast<const uint4*>(Ub + (size_t)row * HIDDEN + ch * 16);
        expand_sts(sm + 1024 + 18432 + row * PITCH + ch * 32, pg);
        expand_sts(sm + 1024 + 36864 + row * PITCH + ch * 32, pu);
    }

    for (int s = 0; s < G1_S; ++s) {
        int b = s & 1;
        CP_WAIT0();
        __syncthreads();

        uint4 hg[2], hu[2];
        bool pre = (s + 1 < G1_S);
        if (pre) {
            int nb = b ^ 1;
            size_t k0 = (size_t)(s + 1) * 128, kw = (size_t)(s + 1) * 64;
#pragma unroll
            for (int j = 0; j < 4; ++j) {
                int task = tid + j * 256, row = task >> 3, ch = task & 7;
                cp16(sb + nb * G1_STG + row * PITCH + ch * 16,
                     Ab + (size_t)row * LDA1 + k0 + ch * 16);
            }
            CP_COMMIT();
#pragma unroll
            for (int j = 0; j < 2; ++j) {
                int task = tid + j * 256, row = task >> 2, ch = task & 3;
                hg[j] = *reinterpret_cast<const uint4*>(Gb + (size_t)row * HIDDEN + kw + ch * 16);
                hu[j] = *reinterpret_cast<const uint4*>(Ub + (size_t)row * HIDDEN + kw + ch * 16);
            }
        }

        const char* st = sm + 1024 + b * G1_STG;
#pragma unroll
        for (int kk = 0; kk < 4; ++kk) {
            uint32_t afr[4][4];
#pragma unroll
            for (int mf = 0; mf < 4; ++mf) {
                const char* p = st + (wm * 64 + mf * 16 + g) * PITCH + kk * 32 + tg * 4;
                afr[mf][0] = *reinterpret_cast<const uint32_t*>(p);
                afr[mf][1] = *reinterpret_cast<const uint32_t*>(p + 8 * PITCH);
                afr[mf][2] = *reinterpret_cast<const uint32_t*>(p + 16);
                afr[mf][3] = *reinterpret_cast<const uint32_t*>(p + 8 * PITCH + 16);
            }
            uint32_t bfg[4][2], bfu[4][2];
#pragma unroll
            for (int nf = 0; nf < 4; ++nf) {
                const char* p = st + 18432 + (wn * 32 + nf * 8 + g) * PITCH + kk * 32 + tg * 4;
                bfg[nf][0] = *reinterpret_cast<const uint32_t*>(p);
                bfg[nf][1] = *reinterpret_cast<const uint32_t*>(p + 16);
                bfu[nf][0] = *reinterpret_cast<const uint32_t*>(p + 18432);
                bfu[nf][1] = *reinterpret_cast<const uint32_t*>(p + 18432 + 16);
            }
#pragma unroll
            for (int mf = 0; mf < 4; ++mf)
#pragma unroll
                for (int nf = 0; nf < 4; ++nf) {
                    MMA_S8(cg[mf][nf], afr[mf], bfg[nf]);
                    MMA_S8(cu[mf][nf], afr[mf], bfu[nf]);
                }
        }

        if (pre) {
            int nb = b ^ 1;
#pragma unroll
            for (int j = 0; j < 2; ++j) {
                int task = tid + j * 256, row = task >> 2, ch = task & 3;
                expand_sts(sm + 1024 + nb * G1_STG + 18432 + row * PITCH + ch * 32, hg[j]);
                expand_sts(sm + 1024 + nb * G1_STG + 36864 + row * PITCH + ch * 32, hu[j]);
            }
        }
    }

    // ---- epilogue: SwiGLU -> g_h fp32, track per-row max|h| ----
#pragma unroll
    for (int mf = 0; mf < 4; ++mf) {
        int row0 = mt * 128 + wm * 64 + mf * 16 + g;
        float rmax0 = 0.f, rmax1 = 0.f;
#pragma unroll
        for (int nf = 0; nf < 4; ++nf) {
            int lc = wn * 32 + nf * 8 + 2 * tg;
            float sg0 = s_ag[lc], sg1 = s_ag[lc + 1];
            float su0 = s_au[lc], su1 = s_au[lc + 1];
            size_t col = (size_t)nt * 128 + lc;
            {
                float gv0 = (float)cg[mf][nf][0] * F1 * sg0;
                float gv1 = (float)cg[mf][nf][1] * F1 * sg1;
                float uv0 = (float)cu[mf][nf][0] * F1 * su0;
                float uv1 = (float)cu[mf][nf][1] * F1 * su1;
                float h0 = gv0 / (1.f + __expf(-gv0)) * uv0;
                float h1 = gv1 / (1.f + __expf(-gv1)) * uv1;
                *reinterpret_cast<float2*>(g_h + (size_t)row0 * INTER + col) = make_float2(h0, h1);
                rmax0 = fmaxf(rmax0, fmaxf(fabsf(h0), fabsf(h1)));
            }
            {
                float gv0 = (float)cg[mf][nf][2] * F1 * sg0;
                float gv1 = (float)cg[mf][nf][3] * F1 * sg1;
                float uv0 = (float)cu[mf][nf][2] * F1 * su0;
                float uv1 = (float)cu[mf][nf][3] * F1 * su1;
                float h0 = gv0 / (1.f + __expf(-gv0)) * uv0;
                float h1 = gv1 / (1.f + __expf(-gv1)) * uv1;
                *reinterpret_cast<float2*>(g_h + (size_t)(row0 + 8) * INTER + col) = make_float2(h0, h1);
                rmax1 = fmaxf(rmax1, fmaxf(fabsf(h0), fabsf(h1)));
            }
        }
        atomicMax(&g_rowmax[row0], __float_as_int(rmax0));
        atomicMax(&g_rowmax[row0 + 8], __float_as_int(rmax1));
    }
}

// ---------------------------------------------------------------------------
// GEMM2: out = h @ Wd^T * ad.  CTA 128M x 256N, warp 64x64.
// Stage: A[128x144] | B[256x144] = 55296 B, x2 stages. 172 stages.
// ---------------------------------------------------------------------------
#define G2_STG  55296
#define G2_SMEM (1024 + 2 * G2_STG)
#define G2_S    172                 /* 11008/64 */

__global__ void __launch_bounds__(256, 1)
gemm2_kernel(const float* __restrict__ ad, float* __restrict__ out) {
    extern __shared__ char sm[];
    const int tid = threadIdx.x;
    const int warp = tid >> 5, lane = tid & 31;
    const int wm = warp >> 2, wn = warp & 3;
    const int g = lane >> 2, tg = lane & 3;

    int bid = blockIdx.x;
    int grp = bid / 128, rem = bid % 128;     // 128 = 8 * 16
    int mt = grp * 8 + (rem & 7);
    int nt = rem >> 3;

    float* s_ad = reinterpret_cast<float*>(sm);
    s_ad[tid] = ad[nt * 256 + tid];

    const int8_t* Ab = g_h8 + (size_t)mt * 128 * LDA2;
    const int8_t* Bb = g_wd8 + (size_t)nt * 256 * INTER;
    const uint32_t sb = smem_u32(sm) + 1024;

    int cc[4][8][4];
#pragma unroll
    for (int i = 0; i < 4; ++i)
#pragma unroll
        for (int j = 0; j < 8; ++j)
#pragma unroll
            for (int k = 0; k < 4; ++k) cc[i][j][k] = 0;

    // prologue
#pragma unroll
    for (int j = 0; j < 4; ++j) {
        int task = tid + j * 256, row = task >> 3, ch = task & 7;
        cp16(sb + row * PITCH + ch * 16, Ab + (size_t)row * LDA2 + ch * 16);
    }
    CP_COMMIT();
#pragma unroll
    for (int j = 0; j < 4; ++j) {
        int task = tid + j * 256, row = task >> 2, ch = task & 3;
        uint4 p = *reinterpret_cast<const uint4*>(Bb + (size_t)row * INTER + ch * 16);
        expand_sts(sm + 1024 + 18432 + row * PITCH + ch * 32, p);
    }

    for (int s = 0; s < G2_S; ++s) {
        int b = s & 1;
        CP_WAIT0();
        __syncthreads();

        uint4 hb[4];
        bool pre = (s + 1 < G2_S);
        if (pre) {
            int nb = b ^ 1;
            size_t k0 = (size_t)(s + 1) * 128, kw = (size_t)(s + 1) * 64;
#pragma unroll
            for (int j = 0; j < 4; ++j) {
                int task = tid + j * 256, row = task >> 3, ch = task & 7;
                cp16(sb + nb * G2_STG + row * PITCH + ch * 16,
                     Ab + (size_t)row * LDA2 + k0 + ch * 16);
            }
            CP_COMMIT();
#pragma unroll
            for (int j = 0; j < 4; ++j) {
                int task = tid + j * 256, row = task >> 2, ch = task & 3;
                hb[j] = *reinterpret_cast<const uint4*>(Bb + (size_t)row * INTER + kw + ch * 16);
            }
        }

        const char* st = sm + 1024 + b * G2_STG;
#pragma unroll
        for (int kk = 0; kk < 4; ++kk) {
            uint32_t afr[4][4];
#pragma unroll
            for (int mf = 0; mf < 4; ++mf) {
                const char* p = st + (wm * 64 + mf * 16 + g) * PITCH + kk * 32 + tg * 4;
                afr[mf][0] = *reinterpret_cast<const uint32_t*>(p);
                afr[mf][1] = *reinterpret_cast<const uint32_t*>(p + 8 * PITCH);
                afr[mf][2] = *reinterpret_cast<const uint32_t*>(p + 16);
                afr[mf][3] = *reinterpret_cast<const uint32_t*>(p + 8 * PITCH + 16);
            }
#pragma unroll
            for (int nf = 0; nf < 8; ++nf) {
                const char* p = st + 18432 + (wn * 64 + nf * 8 + g) * PITCH + kk * 32 + tg * 4;
                uint32_t bf[2];
                bf[0] = *reinterpret_cast<const uint32_t*>(p);
                bf[1] = *reinterpret_cast<const uint32_t*>(p + 16);
#pragma unroll
                for (int mf = 0; mf < 4; ++mf) MMA_S8(cc[mf][nf], afr[mf], bf);
            }
        }

        if (pre) {
            int nb = b ^ 1;
#pragma unroll
            for (int j = 0; j < 4; ++j) {
                int task = tid + j * 256, row = task >> 2, ch = task & 3;
                expand_sts(sm + 1024 + nb * G2_STG + 18432 + row * PITCH + ch * 32, hb[j]);
            }
        }
    }

    // epilogue: out = acc * (s_t/64) * ad[col]
#pragma unroll
    for (int mf = 0; mf < 4; ++mf) {
        int row0 = mt * 128 + wm * 64 + mf * 16 + g;
        float sh0 = g_sh[row0], sh1 = g_sh[row0 + 8];
#pragma unroll
        for (int nf = 0; nf < 8; ++nf) {
            int lc = wn * 64 + nf * 8 + 2 * tg;
            float a0 = s_ad[lc], a1 = s_ad[lc + 1];
            size_t col = (size_t)nt * 256 + lc;
            float v0 = (float)cc[mf][nf][0] * sh0 * a0;
            float v1 = (float)cc[mf][nf][1] * sh0 * a1;
            *reinterpret_cast<float2*>(out + (size_t)row0 * HIDDEN + col) = make_float2(v0, v1);
            float v2 = (float)cc[mf][nf][2] * sh1 * a0;
            float v3 = (float)cc[mf][nf][3] * sh1 * a1;
            *reinterpret_cast<float2*>(out + (size_t)(row0 + 8) * HIDDEN + col) = make_float2(v2, v3);
        }
    }
}

// ---------------------------------------------------------------------------
// Launch
// ---------------------------------------------------------------------------
extern "C" void kernel_launch(void* const* d_in, const int* in_sizes, int n_in,
                              void* d_out, int out_size) {
    (void)in_sizes; (void)n_in; (void)out_size;
    const float* x  = (const float*)d_in[0];
    const float* Wg = (const float*)d_in[1];
    const float* Wu = (const float*)d_in[2];
    const float* Wd = (const float*)d_in[3];
    const float* ag = (const float*)d_in[4];
    const float* au = (const float*)d_in[5];
    const float* ad = (const float*)d_in[6];
    float* out = (float*)d_out;

    cudaFuncSetAttribute(gemm1_kernel, cudaFuncAttributeMaxDynamicSharedMemorySize, G1_SMEM);
    cudaFuncSetAttribute(gemm2_kernel, cudaFuncAttributeMaxDynamicSharedMemorySize, G2_SMEM);

    convert_w_kernel<<<44032, 256>>>(Wg, Wu, Wd);    // 45,088,768 / 1024
    convert_x_kernel<<<32768, 256>>>(x);             // 33,554,432 / 1024 (+rowmax init)
    gemm1_kernel<<<5504, 256, G1_SMEM>>>(ag, au);    // 64 m-tiles x 86 n-tiles
    quantize_h_kernel<<<MTOT, 256>>>();
    gemm2_kernel<<<1024, 256, G2_SMEM>>>(ad, out);   // 64 m-tiles x 16 n-tiles
}

// round 11
// speedup vs baseline: 2.8365x; 2.8365x over previous
#include <cuda_runtime.h>
#include <cuda_fp16.h>
#include <cstdint>

#define HIDDEN 4096
#define INTER  11008
#define MTOT   8192

// ---------------------------------------------------------------------------
// Device-global scratch (allocation rule: __device__ arrays only)
// ---------------------------------------------------------------------------
__device__ __half g_xh[(size_t)MTOT * HIDDEN];   // x hi plane
__device__ __half g_xl[(size_t)MTOT * HIDDEN];   // x lo plane
__device__ __half g_wg16[(size_t)INTER * HIDDEN];
__device__ __half g_wu16[(size_t)INTER * HIDDEN];
__device__ __half g_wd16[(size_t)HIDDEN * INTER];
__device__ __half g_hh[(size_t)MTOT * INTER];    // h hi plane
__device__ __half g_hl[(size_t)MTOT * INTER];    // h lo plane

// ---------------------------------------------------------------------------
// Helpers
// ---------------------------------------------------------------------------
__device__ __forceinline__ uint32_t smem_u32(const void* p) {
    uint32_t a;
    asm("{ .reg .u64 t; cvta.to.shared.u64 t, %1; cvt.u32.u64 %0, t; }"
        : "=r"(a) : "l"(p));
    return a;
}
__device__ __forceinline__ void cp16(uint32_t dst, const void* src) {
    asm volatile("cp.async.cg.shared.global [%0], [%1], 16;" :: "r"(dst), "l"(src));
}
#define CP_COMMIT() asm volatile("cp.async.commit_group;")
#define CP_WAIT0()  asm volatile("cp.async.wait_group 0;")

// m16n8k16 f16 MMA, f32 accumulate (real HMMA on sm_103)
#define MMA_F16(c, a, b)                                                    \
    asm volatile("mma.sync.aligned.m16n8k16.row.col.f32.f16.f16.f32 "       \
        "{%0,%1,%2,%3}, {%4,%5,%6,%7}, {%8,%9}, {%0,%1,%2,%3};"             \
        : "+f"((c)[0]), "+f"((c)[1]), "+f"((c)[2]), "+f"((c)[3])            \
        : "r"((a)[0]), "r"((a)[1]), "r"((a)[2]), "r"((a)[3]),               \
          "r"((b)[0]), "r"((b)[1]))

// ---------------------------------------------------------------------------
// Conversions
// ---------------------------------------------------------------------------
__global__ void convert_w_kernel(const float* __restrict__ wg,
                                 const float* __restrict__ wu,
                                 const float* __restrict__ wd) {
    size_t i = ((size_t)blockIdx.x * blockDim.x + threadIdx.x) * 4;
    if (i >= (size_t)INTER * HIDDEN) return;
    float4 a = *reinterpret_cast<const float4*>(wg + i);
    float4 b = *reinterpret_cast<const float4*>(wu + i);
    float4 c = *reinterpret_cast<const float4*>(wd + i);
    __half2* pg = reinterpret_cast<__half2*>(g_wg16 + i);
    __half2* pu = reinterpret_cast<__half2*>(g_wu16 + i);
    __half2* pd = reinterpret_cast<__half2*>(g_wd16 + i);
    pg[0] = __floats2half2_rn(a.x, a.y); pg[1] = __floats2half2_rn(a.z, a.w);
    pu[0] = __floats2half2_rn(b.x, b.y); pu[1] = __floats2half2_rn(b.z, b.w);
    pd[0] = __floats2half2_rn(c.x, c.y); pd[1] = __floats2half2_rn(c.z, c.w);
}

__global__ void convert_x_kernel(const float* __restrict__ x) {
    size_t i = ((size_t)blockIdx.x * blockDim.x + threadIdx.x) * 4;
    if (i >= (size_t)MTOT * HIDDEN) return;
    float4 v = *reinterpret_cast<const float4*>(x + i);
    float f[4] = {v.x, v.y, v.z, v.w};
    __half h[4], l[4];
#pragma unroll
    for (int q = 0; q < 4; ++q) {
        h[q] = __float2half_rn(f[q]);
        l[q] = __float2half_rn(f[q] - __half2float(h[q]));
    }
    __half2* ph = reinterpret_cast<__half2*>(g_xh + i);
    __half2* pl = reinterpret_cast<__half2*>(g_xl + i);
    ph[0] = __halves2half2(h[0], h[1]); ph[1] = __halves2half2(h[2], h[3]);
    pl[0] = __halves2half2(l[0], l[1]); pl[1] = __halves2half2(l[2], l[3]);
}

// ---------------------------------------------------------------------------
// Shared tiling constants.  K-chunk = 64 f16 = 128 B/row; PITCH 144 B
// (conflict-free: bank = (g*4 + tg + c) mod 32, all-distinct).
// Fragment addressing (m16n8k16): A regs at row {g,g+8}, bytes {tg*4, tg*4+16};
// B regs at n-row (…+g), bytes {tg*4, tg*4+16}.  Same pattern for all tiles.
// ---------------------------------------------------------------------------
#define PITCH   144
#define TILE_B  18432               /* 128 rows * 144 */

// ---------------------------------------------------------------------------
// GEMM1: gate/up + fused SwiGLU -> h (fp16 hi/lo planes).
// CTA 128M x 128N computing BOTH gate and up. 8 warps (2x4), warp 64x32.
// Stage: A_hi | A_lo | Bg | Bu  (18432 B each) = 73728 B, x2 stages.
// ---------------------------------------------------------------------------
#define G1_STG  73728
#define G1_SMEM (1024 + 2 * G1_STG)
#define G1_S    64                  /* 4096/64 */

__global__ void __launch_bounds__(256, 1)
gemm1_kernel(const float* __restrict__ ag, const float* __restrict__ au) {
    extern __shared__ char sm[];
    const int tid = threadIdx.x;
    const int warp = tid >> 5, lane = tid & 31;
    const int wm = warp >> 2, wn = warp & 3;
    const int g = lane >> 2, tg = lane & 3;

    int bid = blockIdx.x;
    int grp = bid / 688, rem = bid % 688;     // 688 = 8 * 86
    int mt = grp * 8 + (rem & 7);
    int nt = rem >> 3;

    float* s_ag = reinterpret_cast<float*>(sm);
    float* s_au = reinterpret_cast<float*>(sm + 512);
    if (tid < 128) {
        s_ag[tid] = ag[nt * 128 + tid];
        s_au[tid] = au[nt * 128 + tid];
    }

    const __half* Ah = g_xh + (size_t)mt * 128 * HIDDEN;
    const __half* Al = g_xl + (size_t)mt * 128 * HIDDEN;
    const __half* Gb = g_wg16 + (size_t)nt * 128 * HIDDEN;
    const __half* Ub = g_wu16 + (size_t)nt * 128 * HIDDEN;
    const uint32_t sb = smem_u32(sm) + 1024;

    float cg[4][4][4], cu[4][4][4];
#pragma unroll
    for (int i = 0; i < 4; ++i)
#pragma unroll
        for (int j = 0; j < 4; ++j)
#pragma unroll
            for (int k = 0; k < 4; ++k) { cg[i][j][k] = 0.f; cu[i][j][k] = 0.f; }

    // ---- prologue: stage 0 (4 cp16 per tile per thread) ----
#pragma unroll
    for (int j = 0; j < 4; ++j) {
        int task = tid + j * 256, row = task >> 3, ch = task & 7;  // 8 halves per chunk
        uint32_t d = sb + row * PITCH + ch * 16;
        const size_t so = (size_t)row * HIDDEN + ch * 8;
        cp16(d,                Ah + so);
        cp16(d + TILE_B,       Al + so);
        cp16(d + 2 * TILE_B,   Gb + so);
        cp16(d + 3 * TILE_B,   Ub + so);
    }
    CP_COMMIT();

    for (int s = 0; s < G1_S; ++s) {
        int b = s & 1;
        CP_WAIT0();
        __syncthreads();

        if (s + 1 < G1_S) {
            int nb = b ^ 1;
            size_t k0 = (size_t)(s + 1) * 64;
#pragma unroll
            for (int j = 0; j < 4; ++j) {
                int task = tid + j * 256, row = task >> 3, ch = task & 7;
                uint32_t d = sb + nb * G1_STG + row * PITCH + ch * 16;
                const size_t so = (size_t)row * HIDDEN + k0 + ch * 8;
                cp16(d,              Ah + so);
                cp16(d + TILE_B,     Al + so);
                cp16(d + 2 * TILE_B, Gb + so);
                cp16(d + 3 * TILE_B, Ub + so);
            }
            CP_COMMIT();
        }

        const char* st = sm + 1024 + b * G1_STG;
#pragma unroll
        for (int kk = 0; kk < 4; ++kk) {
            // B fragments (shared by hi and lo planes)
            uint32_t bfg[4][2], bfu[4][2];
#pragma unroll
            for (int nf = 0; nf < 4; ++nf) {
                const char* p = st + 2 * TILE_B + (wn * 32 + nf * 8 + g) * PITCH + kk * 32 + tg * 4;
                bfg[nf][0] = *reinterpret_cast<const uint32_t*>(p);
                bfg[nf][1] = *reinterpret_cast<const uint32_t*>(p + 16);
                bfu[nf][0] = *reinterpret_cast<const uint32_t*>(p + TILE_B);
                bfu[nf][1] = *reinterpret_cast<const uint32_t*>(p + TILE_B + 16);
            }
            // hi plane
            {
                uint32_t afr[4][4];
#pragma unroll
                for (int mf = 0; mf < 4; ++mf) {
                    const char* p = st + (wm * 64 + mf * 16 + g) * PITCH + kk * 32 + tg * 4;
                    afr[mf][0] = *reinterpret_cast<const uint32_t*>(p);
                    afr[mf][1] = *reinterpret_cast<const uint32_t*>(p + 8 * PITCH);
                    afr[mf][2] = *reinterpret_cast<const uint32_t*>(p + 16);
                    afr[mf][3] = *reinterpret_cast<const uint32_t*>(p + 8 * PITCH + 16);
                }
#pragma unroll
                for (int mf = 0; mf < 4; ++mf)
#pragma unroll
                    for (int nf = 0; nf < 4; ++nf) {
                        MMA_F16(cg[mf][nf], afr[mf], bfg[nf]);
                        MMA_F16(cu[mf][nf], afr[mf], bfu[nf]);
                    }
            }
            // lo plane
            {
                uint32_t afr[4][4];
#pragma unroll
                for (int mf = 0; mf < 4; ++mf) {
                    const char* p = st + TILE_B + (wm * 64 + mf * 16 + g) * PITCH + kk * 32 + tg * 4;
                    afr[mf][0] = *reinterpret_cast<const uint32_t*>(p);
                    afr[mf][1] = *reinterpret_cast<const uint32_t*>(p + 8 * PITCH);
                    afr[mf][2] = *reinterpret_cast<const uint32_t*>(p + 16);
                    afr[mf][3] = *reinterpret_cast<const uint32_t*>(p + 8 * PITCH + 16);
                }
#pragma unroll
                for (int mf = 0; mf < 4; ++mf)
#pragma unroll
                    for (int nf = 0; nf < 4; ++nf) {
                        MMA_F16(cg[mf][nf], afr[mf], bfg[nf]);
                        MMA_F16(cu[mf][nf], afr[mf], bfu[nf]);
                    }
            }
        }
    }

    // ---- epilogue: SwiGLU -> h fp16 hi/lo ----
#pragma unroll
    for (int mf = 0; mf < 4; ++mf) {
        int row0 = mt * 128 + wm * 64 + mf * 16 + g;
#pragma unroll
        for (int nf = 0; nf < 4; ++nf) {
            int lc = wn * 32 + nf * 8 + 2 * tg;
            float sg0 = s_ag[lc], sg1 = s_ag[lc + 1];
            float su0 = s_au[lc], su1 = s_au[lc + 1];
            size_t col = (size_t)nt * 128 + lc;
#pragma unroll
            for (int half_ = 0; half_ < 2; ++half_) {
                int r = row0 + half_ * 8;
                float gv0 = cg[mf][nf][2 * half_]     * sg0;
                float gv1 = cg[mf][nf][2 * half_ + 1] * sg1;
                float uv0 = cu[mf][nf][2 * half_]     * su0;
                float uv1 = cu[mf][nf][2 * half_ + 1] * su1;
                float h0 = gv0 / (1.f + __expf(-gv0)) * uv0;
                float h1 = gv1 / (1.f + __expf(-gv1)) * uv1;
                __half hh0 = __float2half_rn(h0);
                __half hh1 = __float2half_rn(h1);
                __half hl0 = __float2half_rn(h0 - __half2float(hh0));
                __half hl1 = __float2half_rn(h1 - __half2float(hh1));
                *reinterpret_cast<__half2*>(g_hh + (size_t)r * INTER + col) = __halves2half2(hh0, hh1);
                *reinterpret_cast<__half2*>(g_hl + (size_t)r * INTER + col) = __halves2half2(hl0, hl1);
            }
        }
    }
}

// ---------------------------------------------------------------------------
// GEMM2: out = h @ Wd^T * ad.  CTA 128M x 256N, warp 64x64.
// Stage: A_hi | A_lo (18432 each) | B 256x144 (36864) = 73728 B, x2 stages.
// ---------------------------------------------------------------------------
#define G2_STG  73728
#define G2_SMEM (1024 + 2 * G2_STG)
#define G2_S    172                 /* 11008/64 */

__global__ void __launch_bounds__(256, 1)
gemm2_kernel(const float* __restrict__ ad, float* __restrict__ out) {
    extern __shared__ char sm[];
    const int tid = threadIdx.x;
    const int warp = tid >> 5, lane = tid & 31;
    const int wm = warp >> 2, wn = warp & 3;
    const int g = lane >> 2, tg = lane & 3;

    int bid = blockIdx.x;
    int grp = bid / 128, rem = bid % 128;     // 128 = 8 * 16
    int mt = grp * 8 + (rem & 7);
    int nt = rem >> 3;

    float* s_ad = reinterpret_cast<float*>(sm);
    s_ad[tid] = ad[nt * 256 + tid];

    const __half* Ah = g_hh + (size_t)mt * 128 * INTER;
    const __half* Al = g_hl + (size_t)mt * 128 * INTER;
    const __half* Bb = g_wd16 + (size_t)nt * 256 * INTER;
    const uint32_t sb = smem_u32(sm) + 1024;

    float cc[4][8][4];
#pragma unroll
    for (int i = 0; i < 4; ++i)
#pragma unroll
        for (int j = 0; j < 8; ++j)
#pragma unroll
            for (int k = 0; k < 4; ++k) cc[i][j][k] = 0.f;

    // prologue: A tiles (4 each) + B tile (8)
#pragma unroll
    for (int j = 0; j < 4; ++j) {
        int task = tid + j * 256, row = task >> 3, ch = task & 7;
        uint32_t d = sb + row * PITCH + ch * 16;
        const size_t so = (size_t)row * INTER + ch * 8;
        cp16(d,          Ah + so);
        cp16(d + TILE_B, Al + so);
    }
#pragma unroll
    for (int j = 0; j < 8; ++j) {
        int task = tid + j * 256, row = task >> 3, ch = task & 7;
        cp16(sb + 2 * TILE_B + row * PITCH + ch * 16,
             Bb + (size_t)row * INTER + ch * 8);
    }
    CP_COMMIT();

    for (int s = 0; s < G2_S; ++s) {
        int b = s & 1;
        CP_WAIT0();
        __syncthreads();

        if (s + 1 < G2_S) {
            int nb = b ^ 1;
            size_t k0 = (size_t)(s + 1) * 64;
#pragma unroll
            for (int j = 0; j < 4; ++j) {
                int task = tid + j * 256, row = task >> 3, ch = task & 7;
                uint32_t d = sb + nb * G2_STG + row * PITCH + ch * 16;
                const size_t so = (size_t)row * INTER + k0 + ch * 8;
                cp16(d,          Ah + so);
                cp16(d + TILE_B, Al + so);
            }
#pragma unroll
            for (int j = 0; j < 8; ++j) {
                int task = tid + j * 256, row = task >> 3, ch = task & 7;
                cp16(sb + nb * G2_STG + 2 * TILE_B + row * PITCH + ch * 16,
                     Bb + (size_t)row * INTER + k0 + ch * 8);
            }
            CP_COMMIT();
        }

        const char* st = sm + 1024 + b * G2_STG;
#pragma unroll
        for (int kk = 0; kk < 4; ++kk) {
            uint32_t bf[8][2];
#pragma unroll
            for (int nf = 0; nf < 8; ++nf) {
                const char* p = st + 2 * TILE_B + (wn * 64 + nf * 8 + g) * PITCH + kk * 32 + tg * 4;
                bf[nf][0] = *reinterpret_cast<const uint32_t*>(p);
                bf[nf][1] = *reinterpret_cast<const uint32_t*>(p + 16);
            }
            // hi plane
            {
                uint32_t afr[4][4];
#pragma unroll
                for (int mf = 0; mf < 4; ++mf) {
                    const char* p = st + (wm * 64 + mf * 16 + g) * PITCH + kk * 32 + tg * 4;
                    afr[mf][0] = *reinterpret_cast<const uint32_t*>(p);
                    afr[mf][1] = *reinterpret_cast<const uint32_t*>(p + 8 * PITCH);
                    afr[mf][2] = *reinterpret_cast<const uint32_t*>(p + 16);
                    afr[mf][3] = *reinterpret_cast<const uint32_t*>(p + 8 * PITCH + 16);
                }
#pragma unroll
                for (int mf = 0; mf < 4; ++mf)
#pragma unroll
                    for (int nf = 0; nf < 8; ++nf)
                        MMA_F16(cc[mf][nf], afr[mf], bf[nf]);
            }
            // lo plane
            {
                uint32_t afr[4][4];
#pragma unroll
                for (int mf = 0; mf < 4; ++mf) {
                    const char* p = st + TILE_B + (wm * 64 + mf * 16 + g) * PITCH + kk * 32 + tg * 4;
                    afr[mf][0] = *reinterpret_cast<const uint32_t*>(p);
                    afr[mf][1] = *reinterpret_cast<const uint32_t*>(p + 8 * PITCH);
                    afr[mf][2] = *reinterpret_cast<const uint32_t*>(p + 16);
                    afr[mf][3] = *reinterpret_cast<const uint32_t*>(p + 8 * PITCH + 16);
                }
#pragma unroll
                for (int mf = 0; mf < 4; ++mf)
#pragma unroll
                    for (int nf = 0; nf < 8; ++nf)
                        MMA_F16(cc[mf][nf], afr[mf], bf[nf]);
            }
        }
    }

    // epilogue: out = c * ad[col]
#pragma unroll
    for (int mf = 0; mf < 4; ++mf) {
        int row0 = mt * 128 + wm * 64 + mf * 16 + g;
#pragma unroll
        for (int nf = 0; nf < 8; ++nf) {
            int lc = wn * 64 + nf * 8 + 2 * tg;
            float a0 = s_ad[lc], a1 = s_ad[lc + 1];
            size_t col = (size_t)nt * 256 + lc;
            *reinterpret_cast<float2*>(out + (size_t)row0 * HIDDEN + col) =
                make_float2(cc[mf][nf][0] * a0, cc[mf][nf][1] * a1);
            *reinterpret_cast<float2*>(out + (size_t)(row0 + 8) * HIDDEN + col) =
                make_float2(cc[mf][nf][2] * a0, cc[mf][nf][3] * a1);
        }
    }
}

// ---------------------------------------------------------------------------
// Launch
// ---------------------------------------------------------------------------
extern "C" void kernel_launch(void* const* d_in, const int* in_sizes, int n_in,
                              void* d_out, int out_size) {
    (void)in_sizes; (void)n_in; (void)out_size;
    const float* x  = (const float*)d_in[0];
    const float* Wg = (const float*)d_in[1];
    const float* Wu = (const float*)d_in[2];
    const float* Wd = (const float*)d_in[3];
    const float* ag = (const float*)d_in[4];
    const float* au = (const float*)d_in[5];
    const float* ad = (const float*)d_in[6];
    float* out = (float*)d_out;

    cudaFuncSetAttribute(gemm1_kernel, cudaFuncAttributeMaxDynamicSharedMemorySize, G1_SMEM);
    cudaFuncSetAttribute(gemm2_kernel, cudaFuncAttributeMaxDynamicSharedMemorySize, G2_SMEM);

    convert_w_kernel<<<44032, 256>>>(Wg, Wu, Wd);
    convert_x_kernel<<<32768, 256>>>(x);
    gemm1_kernel<<<5504, 256, G1_SMEM>>>(ag, au);   // 64 m x 86 n
    gemm2_kernel<<<1024, 256, G2_SMEM>>>(ad, out);  // 64 m x 16 n
}